// round 1
// baseline (speedup 1.0000x reference)
#include <cuda_runtime.h>
#include <cuda_fp16.h>
#include <cstdint>

// Problem shape (fixed for this dataset entry)
#define M_DIM 8192
#define N_DIM 11008
#define K_DIM 4096
#define KP    (K_DIM / 8)   // 512 packed rows in qweight
#define NZ    (N_DIM / 8)   // 1376 packed cols in qzeros

// GEMM tiling
#define BM 128
#define BN 128
#define BK 32
#define ASTRIDE 40    // BK + 8 halves  (80 bytes/row, 16B-aligned, conflict-free ldmatrix)
#define BSTRIDE 136   // BN + 8 halves  (272 bytes/row)

// Scratch (device globals — allocation-free)
__device__ __half g_W[(size_t)K_DIM * N_DIM];   // dequantized weights, fp16, row-major [K][N]
__device__ __half g_X[(size_t)M_DIM * K_DIM];   // x converted to fp16, row-major [M][K]

// ---------------------------------------------------------------------------
// Dequant: one thread per qweight word (8 K-values x 1 N-col)
// ---------------------------------------------------------------------------
__global__ void dequant_kernel(const int* __restrict__ qw,
                               const float* __restrict__ scales,
                               const int* __restrict__ qz) {
    int idx = blockIdx.x * blockDim.x + threadIdx.x;
    if (idx >= KP * N_DIM) return;
    int n  = idx % N_DIM;
    int kp = idx / N_DIM;
    int g  = kp >> 4;                       // group = (kp*8)/128
    unsigned w  = (unsigned)qw[idx];        // qweight[kp][n]
    unsigned zw = (unsigned)qz[g * NZ + (n >> 3)];
    float z = (float)((zw >> ((n & 7) * 4)) & 0xF);
    float s = scales[g * N_DIM + n];
    size_t base = (size_t)(kp * 8) * N_DIM + n;
#pragma unroll
    for (int j = 0; j < 8; j++) {
        float q = (float)((w >> (4 * j)) & 0xF);
        g_W[base + (size_t)j * N_DIM] = __float2half(s * (q - z));
    }
}

// ---------------------------------------------------------------------------
// x fp32 -> fp16
// ---------------------------------------------------------------------------
__global__ void convert_x_kernel(const float* __restrict__ x) {
    int i = blockIdx.x * blockDim.x + threadIdx.x;   // one float4 per thread
    float4 v = ((const float4*)x)[i];
    __half2* o = (__half2*)g_X;
    o[2 * i]     = __floats2half2_rn(v.x, v.y);
    o[2 * i + 1] = __floats2half2_rn(v.z, v.w);
}

// ---------------------------------------------------------------------------
// mma.sync fp16 GEMM helpers
// ---------------------------------------------------------------------------
__device__ __forceinline__ void cp_async16(uint32_t dst, const void* src) {
    asm volatile("cp.async.cg.shared.global [%0], [%1], 16;\n" :: "r"(dst), "l"(src));
}
__device__ __forceinline__ void cp_commit() {
    asm volatile("cp.async.commit_group;\n" ::: "memory");
}
__device__ __forceinline__ void cp_wait1() {
    asm volatile("cp.async.wait_group 1;\n" ::: "memory");
}
__device__ __forceinline__ void ldmatrix_x4(uint32_t* r, uint32_t addr) {
    asm volatile("ldmatrix.sync.aligned.m8n8.x4.shared.b16 {%0,%1,%2,%3}, [%4];"
                 : "=r"(r[0]), "=r"(r[1]), "=r"(r[2]), "=r"(r[3]) : "r"(addr));
}
__device__ __forceinline__ void ldmatrix_x4_t(uint32_t* r, uint32_t addr) {
    asm volatile("ldmatrix.sync.aligned.m8n8.x4.trans.shared.b16 {%0,%1,%2,%3}, [%4];"
                 : "=r"(r[0]), "=r"(r[1]), "=r"(r[2]), "=r"(r[3]) : "r"(addr));
}
__device__ __forceinline__ void mma16816(float* c, const uint32_t* a, const uint32_t* b) {
    asm volatile("mma.sync.aligned.m16n8k16.row.col.f32.f16.f16.f32 "
                 "{%0,%1,%2,%3}, {%4,%5,%6,%7}, {%8,%9}, {%0,%1,%2,%3};"
                 : "+f"(c[0]), "+f"(c[1]), "+f"(c[2]), "+f"(c[3])
                 : "r"(a[0]), "r"(a[1]), "r"(a[2]), "r"(a[3]), "r"(b[0]), "r"(b[1]));
}

// ---------------------------------------------------------------------------
// GEMM: C[M,N] = g_X[M,K] * g_W[K,N], fp16 inputs, fp32 accumulate
// Block 128x128x32, 8 warps as 4(m) x 2(n), warp tile 32x64, 2-stage cp.async
// ---------------------------------------------------------------------------
__global__ void __launch_bounds__(256, 2)
gemm_kernel(float* __restrict__ out) {
    __shared__ __half sA[2][BM * ASTRIDE];
    __shared__ __half sB[2][BK * BSTRIDE];

    const int tid  = threadIdx.x;
    const int lane = tid & 31;
    const int warp = tid >> 5;
    const int wrow = warp >> 1;   // 0..3
    const int wcol = warp & 1;    // 0..1
    const int bm = blockIdx.y * BM;
    const int bn = blockIdx.x * BN;

    const __half* gA = g_X + (size_t)bm * K_DIM;
    const __half* gB = g_W + bn;

    const uint32_t sA0 = (uint32_t)__cvta_generic_to_shared(&sA[0][0]);
    const uint32_t sB0 = (uint32_t)__cvta_generic_to_shared(&sB[0][0]);

    float acc[2][8][4];
#pragma unroll
    for (int mi = 0; mi < 2; mi++)
#pragma unroll
        for (int ni = 0; ni < 8; ni++)
#pragma unroll
            for (int j = 0; j < 4; j++) acc[mi][ni][j] = 0.0f;

    // Precompute this thread's cp.async assignments (2 chunks for A, 2 for B)
    const int ar0 = (tid)            >> 2, ak0 = (tid)            & 3;
    const int ar1 = (tid + 256)      >> 2, ak1 = (tid + 256)      & 3;
    const int br0 = (tid)            >> 4, bn0 = (tid)            & 15;
    const int br1 = (tid + 256)      >> 4, bn1 = (tid + 256)      & 15;

#define LOAD_TILE(stage, kt)                                                          \
    do {                                                                              \
        uint32_t aOff = sA0 + (stage) * (BM * ASTRIDE * 2);                           \
        uint32_t bOff = sB0 + (stage) * (BK * BSTRIDE * 2);                           \
        cp_async16(aOff + (ar0 * ASTRIDE + ak0 * 8) * 2,                              \
                   gA + (size_t)ar0 * K_DIM + (kt) * BK + ak0 * 8);                   \
        cp_async16(aOff + (ar1 * ASTRIDE + ak1 * 8) * 2,                              \
                   gA + (size_t)ar1 * K_DIM + (kt) * BK + ak1 * 8);                   \
        cp_async16(bOff + (br0 * BSTRIDE + bn0 * 8) * 2,                              \
                   gB + (size_t)((kt) * BK + br0) * N_DIM + bn0 * 8);                 \
        cp_async16(bOff + (br1 * BSTRIDE + bn1 * 8) * 2,                              \
                   gB + (size_t)((kt) * BK + br1) * N_DIM + bn1 * 8);                 \
    } while (0)

    const int KT = K_DIM / BK;   // 128

    LOAD_TILE(0, 0);
    cp_commit();

    for (int kt = 0; kt < KT; kt++) {
        const int st = kt & 1;
        if (kt + 1 < KT) LOAD_TILE((kt + 1) & 1, kt + 1);
        cp_commit();
        cp_wait1();              // tile kt resident (completion is FIFO)
        __syncthreads();

        const uint32_t aBase = sA0 + st * (BM * ASTRIDE * 2);
        const uint32_t bBase = sB0 + st * (BK * BSTRIDE * 2);

#pragma unroll
        for (int ks = 0; ks < 2; ks++) {
            uint32_t afr[2][4];
#pragma unroll
            for (int mi = 0; mi < 2; mi++) {
                int row = wrow * 32 + mi * 16 + (lane & 15);
                int col = ks * 16 + (lane >> 4) * 8;
                ldmatrix_x4(afr[mi], aBase + (row * ASTRIDE + col) * 2);
            }
            uint32_t bfr[8][2];
#pragma unroll
            for (int p = 0; p < 4; p++) {
                int row = ks * 16 + (lane & 15);
                int col = wcol * 64 + p * 16 + (lane >> 4) * 8;
                uint32_t r[4];
                ldmatrix_x4_t(r, bBase + (row * BSTRIDE + col) * 2);
                bfr[2 * p][0] = r[0]; bfr[2 * p][1] = r[1];
                bfr[2 * p + 1][0] = r[2]; bfr[2 * p + 1][1] = r[3];
            }
#pragma unroll
            for (int mi = 0; mi < 2; mi++)
#pragma unroll
                for (int ni = 0; ni < 8; ni++)
                    mma16816(acc[mi][ni], afr[mi], bfr[ni]);
        }
        __syncthreads();         // all reads of stage st done before next overwrite
    }

    // Epilogue: fp32 direct to gmem (float2 per fragment half)
#pragma unroll
    for (int mi = 0; mi < 2; mi++) {
#pragma unroll
        for (int ni = 0; ni < 8; ni++) {
            int r0 = bm + wrow * 32 + mi * 16 + (lane >> 2);
            int c0 = bn + wcol * 64 + ni * 8 + (lane & 3) * 2;
            *(float2*)(out + (size_t)r0 * N_DIM + c0) =
                make_float2(acc[mi][ni][0], acc[mi][ni][1]);
            *(float2*)(out + (size_t)(r0 + 8) * N_DIM + c0) =
                make_float2(acc[mi][ni][2], acc[mi][ni][3]);
        }
    }
#undef LOAD_TILE
}

// ---------------------------------------------------------------------------
extern "C" void kernel_launch(void* const* d_in, const int* in_sizes, int n_in,
                              void* d_out, int out_size) {
    (void)in_sizes; (void)n_in; (void)out_size;
    const float* x      = (const float*)d_in[0];
    const int*   qw     = (const int*)d_in[1];
    const float* scales = (const float*)d_in[2];
    const int*   qz     = (const int*)d_in[3];
    float* out = (float*)d_out;

    dequant_kernel<<<(KP * N_DIM + 255) / 256, 256>>>(qw, scales, qz);
    convert_x_kernel<<<(M_DIM * K_DIM / 4) / 256, 256>>>(x);
    dim3 grid(N_DIM / BN, M_DIM / BM);   // (86, 64)
    gemm_kernel<<<grid, 256>>>(out);
}